// round 13
// baseline (speedup 1.0000x reference)
#include <cuda_runtime.h>
#include <cstdint>

#define S_SUBJ   4
#define B_BATCH  64
#define K_VOX    40000
#define OUT_DIMN 768
#define V_VOX    (64*64*48)

#define OT      128          // outputs per block tile
#define MT      16           // samples per block tile (= MMA M)
#define KSPLIT  25
#define KCHUNK  1600         // 40000 / 25
#define KC      64           // K per smem chunk
#define NITER   (KCHUNK/KC)  // 25
#define STAGES  3

#define ROWB    272          // padded row pitch in bytes (256 data + 16 pad)
#define NROWS   (OT+MT)      // 144 rows per stage
#define STAGE_B (NROWS*ROWB) // 39168 B
#define TXBYTES (NROWS*256)  // 36864 B per chunk
#define WSTRIDE 68           // row pitch in floats
#define SMEM_BYTES (STAGES*STAGE_B)   // 117504 B -> 1 block/SM

// -------- device scratch (allocation-free per harness rules) --------
__device__ float g_G[(size_t)B_BATCH * K_VOX];
__device__ int   g_subj[B_BATCH];
__device__ int   g_order[B_BATCH];
__device__ int   g_slotsubj[B_BATCH];
__device__ int   g_off[S_SUBJ + 1];

// -------- 1) grouping + dtype detection --------
__global__ void setup_kernel(const void* idp) {
    if (threadIdx.x != 0) return;
    const int* w = (const int*)idp;
    bool is64 = true;
    for (int i = 1; i < B_BATCH; i += 2) {
        if (w[i] != 0) { is64 = false; break; }
    }
    int subj[B_BATCH];
    for (int b = 0; b < B_BATCH; b++) {
        int s = is64 ? w[2 * b] : w[b];
        subj[b] = s;
        g_subj[b] = s;
    }
    int cnt[S_SUBJ];
    for (int s = 0; s < S_SUBJ; s++) cnt[s] = 0;
    for (int b = 0; b < B_BATCH; b++) cnt[subj[b]]++;
    int off = 0, pos[S_SUBJ];
    for (int s = 0; s < S_SUBJ; s++) { g_off[s] = off; pos[s] = off; off += cnt[s]; }
    g_off[S_SUBJ] = off;
    for (int b = 0; b < B_BATCH; b++) {
        int s = subj[b];
        int p = pos[s]++;
        g_order[p] = b;
        g_slotsubj[p] = s;
    }
}

// -------- 2) out = bias[subj[b]] --------
__global__ void init_out_kernel(float* out, const float* bias) {
    int i = blockIdx.x * blockDim.x + threadIdx.x;
    if (i >= B_BATCH * OUT_DIMN) return;
    int b = i / OUT_DIMN;
    int o = i - b * OUT_DIMN;
    out[i] = bias[g_subj[b] * OUT_DIMN + o];
}

// -------- 3) gather (pre-rounds G to tf32-RNA: A-side MMA truncation exact) ----
__global__ void gather_kernel(const float* __restrict__ fmri, const int* __restrict__ idx) {
    int slot = blockIdx.y;
    int k = blockIdx.x * blockDim.x + threadIdx.x;
    if (k >= K_VOX) return;
    int b = g_order[slot];
    int s = g_slotsubj[slot];
    float v = fmri[(size_t)b * V_VOX + idx[s * K_VOX + k]];
    uint32_t bits;
    asm("cvt.rna.tf32.f32 %0, %1;" : "=r"(bits) : "f"(v));
    g_G[(size_t)slot * K_VOX + k] = __uint_as_float(bits);
}

// -------- asm helpers --------
__device__ __forceinline__ uint32_t smem_u32(const void* p) {
    uint32_t a;
    asm("{ .reg .u64 t; cvta.to.shared.u64 t, %1; cvt.u32.u64 %0, t; }" : "=r"(a) : "l"(p));
    return a;
}
__device__ __forceinline__ void bulk_g2s(uint32_t dst, const void* src, uint32_t mbar) {
    asm volatile(
        "cp.async.bulk.shared::cluster.global.mbarrier::complete_tx::bytes "
        "[%0], [%1], %2, [%3];"
        :: "r"(dst), "l"(src), "r"(256u), "r"(mbar) : "memory");
}
__device__ __forceinline__ void mbar_init(uint32_t a, uint32_t c) {
    asm volatile("mbarrier.init.shared.b64 [%0], %1;" :: "r"(a), "r"(c) : "memory");
}
__device__ __forceinline__ void mbar_expect(uint32_t a, uint32_t bytes) {
    asm volatile("mbarrier.arrive.expect_tx.shared.b64 _, [%0], %1;"
                 :: "r"(a), "r"(bytes) : "memory");
}
__device__ __forceinline__ void mbar_wait(uint32_t a, int parity) {
    asm volatile(
        "{\n\t.reg .pred P;\n\t"
        "W_%=:\n\t"
        "mbarrier.try_wait.parity.acquire.cta.shared::cta.b64 P, [%0], %1, 0x989680;\n\t"
        "@!P bra W_%=;\n\t}"
        :: "r"(a), "r"(parity) : "memory");
}
__device__ __forceinline__ uint32_t tf32_rna(float f) {
    uint32_t r;
    asm("cvt.rna.tf32.f32 %0, %1;" : "=r"(r) : "f"(f));
    return r;
}
__device__ __forceinline__ void mma_tf32(float* c, uint32_t a0, uint32_t a1,
                                         uint32_t a2, uint32_t a3,
                                         uint32_t b0, uint32_t b1) {
    asm volatile(
        "mma.sync.aligned.m16n8k8.row.col.f32.tf32.tf32.f32 "
        "{%0,%1,%2,%3}, {%4,%5,%6,%7}, {%8,%9}, {%0,%1,%2,%3};"
        : "+f"(c[0]), "+f"(c[1]), "+f"(c[2]), "+f"(c[3])
        : "r"(a0), "r"(a1), "r"(a2), "r"(a3), "r"(b0), "r"(b1));
}

// -------- 4) grouped GEMM via mma.sync tf32, TMA-bulk-fed --------
// OT=128 x MT=16 x KCHUNK. Warp w: o-half (w&1)*64, k-quarter kq=w>>1.
// 3-stage pipeline: 144 x 256B cp.async.bulk per chunk -> per-stage mbarrier
// (expect_tx). __syncthreads at loop top gates stage reuse.
__global__ void __launch_bounds__(256, 1) gemm_kernel(const float* __restrict__ Wt,
                                                      float* __restrict__ out) {
    extern __shared__ __align__(16) float smem[];
    __shared__ __align__(16) unsigned long long s_mbar[STAGES];

    int tid = threadIdx.x;
    int warp = tid >> 5;
    int lane = tid & 31;

    int s = blockIdx.y >> 2;
    int mtile = (blockIdx.y & 3) * MT;
    int off = g_off[s];
    int count = g_off[s + 1] - off;
    int rows = count - mtile;
    if (rows <= 0) return;
    if (rows > MT) rows = MT;

    int otile = blockIdx.x * OT;
    size_t k0 = (size_t)blockIdx.z * KCHUNK;

    uint32_t smem_b = smem_u32(smem);
    uint32_t mbar0 = smem_u32(&s_mbar[0]);

    if (tid < STAGES) mbar_init(mbar0 + tid * 8, 1);
    __syncthreads();

    // ---- per-thread transfer source (row tid: W rows 0..127, G rows 128..143) --
    const float* srcbase = nullptr;
    if (tid < OT) {
        srcbase = Wt + (size_t)(s * OUT_DIMN + otile + tid) * K_VOX + k0;
    } else if (tid < NROWS) {
        int g = tid - OT;
        int mglob = mtile + g;
        int slot = off + (mglob < count ? mglob : count - 1);
        srcbase = g_G + (size_t)slot * K_VOX + k0;
    }
    uint32_t dstoff = tid * ROWB;

    // ---- compute map ----
    int ohalf = (warp & 1) * 64;
    int kq = warp >> 1;                 // 0..3
    int lg = lane >> 2;                 // 0..7
    int lt = lane & 3;                  // 0..3

    float acc[8][4];
#pragma unroll
    for (int j = 0; j < 8; j++)
#pragma unroll
        for (int r = 0; r < 4; r++) acc[j][r] = 0.f;

#define ISSUE(IT, ST)                                                          \
    do {                                                                       \
        uint32_t mb = mbar0 + (ST) * 8;                                        \
        if (tid == 0) mbar_expect(mb, TXBYTES);                                \
        if (tid < NROWS)                                                       \
            bulk_g2s(smem_b + (ST) * STAGE_B + dstoff, srcbase + (IT) * KC, mb); \
    } while (0)

    ISSUE(0, 0);
    ISSUE(1, 1);

    int st = 0, wst = 2;

    for (int it = 0; it < NITER; it++) {
        __syncthreads();                 // all warps done with stage wst's old data
        if (it + 2 < NITER) {
            ISSUE(it + 2, wst);
            wst = (wst == STAGES - 1) ? 0 : wst + 1;
        }
        mbar_wait(mbar0 + st * 8, (it / 3) & 1);

        const float* ws = smem + st * (STAGE_B / 4);
        const float* gs = ws + OT * WSTRIDE;
        st = (st == STAGES - 1) ? 0 : st + 1;

#pragma unroll
        for (int kk = 0; kk < 2; kk++) {
            int kb = (kq + kk * 4) * 8 + lt;
            const float* ga = &gs[lg * WSTRIDE + kb];
            uint32_t a0 = __float_as_uint(ga[0]);
            uint32_t a1 = __float_as_uint(ga[8 * WSTRIDE]);
            uint32_t a2 = __float_as_uint(ga[4]);
            uint32_t a3 = __float_as_uint(ga[8 * WSTRIDE + 4]);
            const float* wb = &ws[(ohalf + lg) * WSTRIDE + kb];
#pragma unroll
            for (int j = 0; j < 8; j++) {
                uint32_t b0 = tf32_rna(wb[j * 8 * WSTRIDE]);
                uint32_t b1 = tf32_rna(wb[j * 8 * WSTRIDE + 4]);
                mma_tf32(acc[j], a0, a1, a2, a3, b0, b1);
            }
        }
    }
#undef ISSUE

    // ---- kq reduction in smem, then atomics ----
    __syncthreads();
    const int RS = 132;
    float* red = smem;   // 4*16*132 = 8448 floats, well inside stage area
#pragma unroll
    for (int j = 0; j < 8; j++) {
        int o = ohalf + j * 8 + lt * 2;
        float* r0 = &red[(kq * MT + lg) * RS + o];
        r0[0] = acc[j][0];
        r0[1] = acc[j][1];
        r0[8 * RS] = acc[j][2];
        r0[8 * RS + 1] = acc[j][3];
    }
    __syncthreads();
    int rm = tid >> 4;
    int oc = (tid & 15) * 8;
    if (rm < rows) {
        float sum[8];
#pragma unroll
        for (int i = 0; i < 8; i++) sum[i] = 0.f;
#pragma unroll
        for (int q = 0; q < 4; q++) {
            const float* rp = &red[(q * MT + rm) * RS + oc];
#pragma unroll
            for (int i = 0; i < 8; i++) sum[i] += rp[i];
        }
        int b = g_order[off + mtile + rm];
        float* op = &out[b * OUT_DIMN + otile + oc];
#pragma unroll
        for (int i = 0; i < 8; i++) atomicAdd(op + i, sum[i]);
    }
}

extern "C" void kernel_launch(void* const* d_in, const int* in_sizes, int n_in,
                              void* d_out, int out_size) {
    (void)in_sizes; (void)n_in; (void)out_size;
    const void*  idp  = d_in[0];
    const float* fmri = (const float*)d_in[1];
    const int*   idx  = (const int*)d_in[2];
    const float* Wt   = (const float*)d_in[3];
    const float* bias = (const float*)d_in[4];
    float* out = (float*)d_out;

    static bool attr_set = false;
    if (!attr_set) {
        cudaFuncSetAttribute(gemm_kernel,
                             cudaFuncAttributeMaxDynamicSharedMemorySize, SMEM_BYTES);
        attr_set = true;
    }

    setup_kernel<<<1, 32>>>(idp);
    init_out_kernel<<<(B_BATCH * OUT_DIMN + 255) / 256, 256>>>(out, bias);
    gather_kernel<<<dim3((K_VOX + 255) / 256, B_BATCH), 256>>>(fmri, idx);
    gemm_kernel<<<dim3(OUT_DIMN / OT, 16, KSPLIT), 256, SMEM_BYTES>>>(Wt, out);
}

// round 14
// speedup vs baseline: 1.5882x; 1.5882x over previous
#include <cuda_runtime.h>
#include <cstdint>

#define S_SUBJ   4
#define B_BATCH  64
#define K_VOX    40000
#define OUT_DIMN 768
#define V_VOX    (64*64*48)

#define OT      128          // outputs per block tile
#define MT      16           // samples per block tile (= MMA M)
#define KSPLIT  50
#define KCHUNK  800          // 40000 / 50
#define KC      32           // K per smem chunk
#define NITER   (KCHUNK/KC)  // 25
#define STAGES  3

#define WSTRIDE 36           // padded row stride (floats) -> conflict-free LDS.32
#define WS_F    (OT*WSTRIDE) // 4608 floats
#define GS_F    (MT*WSTRIDE) // 576 floats
#define STAGE_F (WS_F+GS_F)  // 5184 floats
#define STAGE_B (STAGE_F*4)  // 20736 B
#define SMEM_BYTES (STAGES*STAGE_B)   // 62208 B -> 3 blocks/SM

// -------- device scratch (allocation-free per harness rules) --------
__device__ float g_G[(size_t)B_BATCH * K_VOX];
__device__ int   g_subj[B_BATCH];
__device__ int   g_order[B_BATCH];
__device__ int   g_slotsubj[B_BATCH];
__device__ int   g_off[S_SUBJ + 1];

// -------- 1) grouping + dtype detection --------
__global__ void setup_kernel(const void* idp) {
    if (threadIdx.x != 0) return;
    const int* w = (const int*)idp;
    bool is64 = true;
    for (int i = 1; i < B_BATCH; i += 2) {
        if (w[i] != 0) { is64 = false; break; }
    }
    int subj[B_BATCH];
    for (int b = 0; b < B_BATCH; b++) {
        int s = is64 ? w[2 * b] : w[b];
        subj[b] = s;
        g_subj[b] = s;
    }
    int cnt[S_SUBJ];
    for (int s = 0; s < S_SUBJ; s++) cnt[s] = 0;
    for (int b = 0; b < B_BATCH; b++) cnt[subj[b]]++;
    int off = 0, pos[S_SUBJ];
    for (int s = 0; s < S_SUBJ; s++) { g_off[s] = off; pos[s] = off; off += cnt[s]; }
    g_off[S_SUBJ] = off;
    for (int b = 0; b < B_BATCH; b++) {
        int s = subj[b];
        int p = pos[s]++;
        g_order[p] = b;
        g_slotsubj[p] = s;
    }
}

// -------- 2) out = bias[subj[b]] --------
__global__ void init_out_kernel(float* out, const float* bias) {
    int i = blockIdx.x * blockDim.x + threadIdx.x;
    if (i >= B_BATCH * OUT_DIMN) return;
    int b = i / OUT_DIMN;
    int o = i - b * OUT_DIMN;
    out[i] = bias[g_subj[b] * OUT_DIMN + o];
}

// -------- 3) gather (pre-rounds G to tf32-RNA: A-side MMA truncation exact) ----
__global__ void gather_kernel(const float* __restrict__ fmri, const int* __restrict__ idx) {
    int slot = blockIdx.y;
    int k = blockIdx.x * blockDim.x + threadIdx.x;
    if (k >= K_VOX) return;
    int b = g_order[slot];
    int s = g_slotsubj[slot];
    float v = fmri[(size_t)b * V_VOX + idx[s * K_VOX + k]];
    uint32_t bits;
    asm("cvt.rna.tf32.f32 %0, %1;" : "=r"(bits) : "f"(v));
    g_G[(size_t)slot * K_VOX + k] = __uint_as_float(bits);
}

// -------- asm helpers --------
__device__ __forceinline__ void cp_async16(uint32_t smem_addr, const void* gptr) {
    asm volatile("cp.async.cg.shared.global [%0], [%1], 16;" :: "r"(smem_addr), "l"(gptr));
}
__device__ __forceinline__ void cp_commit() { asm volatile("cp.async.commit_group;"); }
__device__ __forceinline__ void cp_wait1() { asm volatile("cp.async.wait_group 1;"); }
__device__ __forceinline__ void cp_wait0() { asm volatile("cp.async.wait_group 0;"); }
__device__ __forceinline__ uint32_t tf32_rna(float f) {
    uint32_t r;
    asm("cvt.rna.tf32.f32 %0, %1;" : "=r"(r) : "f"(f));
    return r;
}
__device__ __forceinline__ void mma_tf32(float* c, uint32_t a0, uint32_t a1,
                                         uint32_t a2, uint32_t a3,
                                         uint32_t b0, uint32_t b1) {
    asm volatile(
        "mma.sync.aligned.m16n8k8.row.col.f32.tf32.tf32.f32 "
        "{%0,%1,%2,%3}, {%4,%5,%6,%7}, {%8,%9}, {%0,%1,%2,%3};"
        : "+f"(c[0]), "+f"(c[1]), "+f"(c[2]), "+f"(c[3])
        : "r"(a0), "r"(a1), "r"(a2), "r"(a3), "r"(b0), "r"(b1));
}

// -------- 4) grouped GEMM via mma.sync tf32 (HMMA) --------
// OT=128 x MT=16 x KCHUNK(800). Warp w: o-half (w&1)*64, k-step kq=w>>1.
// 3-stage cp.async pipeline (depth 2), 3 blocks/SM. Tail waits graduated.
__global__ void __launch_bounds__(256, 3) gemm_kernel(const float* __restrict__ Wt,
                                                      float* __restrict__ out) {
    extern __shared__ __align__(16) float smem[];

    int tid = threadIdx.x;
    int warp = tid >> 5;
    int lane = tid & 31;

    int s = blockIdx.y >> 2;
    int mtile = (blockIdx.y & 3) * MT;
    int off = g_off[s];
    int count = g_off[s + 1] - off;
    int rows = count - mtile;
    if (rows <= 0) return;
    if (rows > MT) rows = MT;

    int otile = blockIdx.x * OT;
    size_t k0 = (size_t)blockIdx.z * KCHUNK;

    uint32_t smem_b;
    asm("{ .reg .u64 t; cvta.to.shared.u64 t, %1; cvt.u32.u64 %0, t; }"
        : "=r"(smem_b) : "l"(smem));

    // ---- staging map: thread -> cell (t&7), row base (t>>3 : 0..31) ----
    int cell = tid & 7;
    int rb = tid >> 3;                  // 0..31
    const float* wbase = Wt + (size_t)(s * OUT_DIMN + otile + rb) * K_VOX + k0 + cell * 4;
    int mglob = mtile + rb;             // G row (only rb<16 issues G)
    int slot = off + (mglob < count ? mglob : count - 1);
    const float* gbase = g_G + (size_t)slot * K_VOX + k0 + cell * 4;
    uint32_t wdoff = rb * (WSTRIDE * 4) + cell * 16;

    // ---- compute map ----
    int ohalf = (warp & 1) * 64;
    int kq = warp >> 1;                 // k8-step 0..3
    int lg = lane >> 2;                 // 0..7
    int lt = lane & 3;                  // 0..3

    float acc[8][4];
#pragma unroll
    for (int j = 0; j < 8; j++)
#pragma unroll
        for (int r = 0; r < 4; r++) acc[j][r] = 0.f;

#define ISSUE(IT, ST)                                                          \
    do {                                                                       \
        uint32_t wsb = smem_b + (ST) * STAGE_B;                                \
        const float* wsrc = wbase + (IT) * KC;                                 \
        _Pragma("unroll")                                                      \
        for (int q = 0; q < 4; q++)                                            \
            cp_async16(wsb + wdoff + q * (32 * WSTRIDE * 4),                   \
                       wsrc + (size_t)(32 * q) * K_VOX);                       \
        if (rb < MT)                                                           \
            cp_async16(wsb + WS_F * 4 + wdoff, gbase + (IT) * KC);             \
        cp_commit();                                                           \
    } while (0)
    // global W row = otile + rb + 32q  matches smem row rb + 32q.

    ISSUE(0, 0);
    ISSUE(1, 1);

    int st = 0, wst = 2;

    for (int it = 0; it < NITER; it++) {
        // pending before wait: min(it+1, NITER-1) - it + 1
        if (it + 2 <= NITER) cp_wait1();   // 2 pending -> chunk it landed
        else                 cp_wait0();   // last chunk
        __syncthreads();
        if (it + 2 < NITER) {
            ISSUE(it + 2, wst);
            wst = (wst == STAGES - 1) ? 0 : wst + 1;
        }

        const float* ws = smem + st * STAGE_F;
        const float* gs = ws + WS_F;
        st = (st == STAGES - 1) ? 0 : st + 1;

        {
            int kb = kq * 8 + lt;
            const float* ga = &gs[lg * WSTRIDE + kb];
            uint32_t a0 = __float_as_uint(ga[0]);
            uint32_t a1 = __float_as_uint(ga[8 * WSTRIDE]);
            uint32_t a2 = __float_as_uint(ga[4]);
            uint32_t a3 = __float_as_uint(ga[8 * WSTRIDE + 4]);
            const float* wb = &ws[(ohalf + lg) * WSTRIDE + kb];
#pragma unroll
            for (int j = 0; j < 8; j++) {
                uint32_t b0 = tf32_rna(wb[j * 8 * WSTRIDE]);
                uint32_t b1 = tf32_rna(wb[j * 8 * WSTRIDE + 4]);
                mma_tf32(acc[j], a0, a1, a2, a3, b0, b1);
            }
        }
    }
#undef ISSUE

    // ---- kq reduction in smem, then atomics ----
    __syncthreads();
    const int RS = 132;
    float* red = smem;   // 4*16*132 = 8448 floats (< STAGES*STAGE_F)
#pragma unroll
    for (int j = 0; j < 8; j++) {
        int o = ohalf + j * 8 + lt * 2;
        float* r0 = &red[(kq * MT + lg) * RS + o];
        r0[0] = acc[j][0];
        r0[1] = acc[j][1];
        r0[8 * RS] = acc[j][2];
        r0[8 * RS + 1] = acc[j][3];
    }
    __syncthreads();
    int rm = tid >> 4;
    int oc = (tid & 15) * 8;
    if (rm < rows) {
        float sum[8];
#pragma unroll
        for (int i = 0; i < 8; i++) sum[i] = 0.f;
#pragma unroll
        for (int q = 0; q < 4; q++) {
            const float* rp = &red[(q * MT + rm) * RS + oc];
#pragma unroll
            for (int i = 0; i < 8; i++) sum[i] += rp[i];
        }
        int b = g_order[off + mtile + rm];
        float* op = &out[b * OUT_DIMN + otile + oc];
#pragma unroll
        for (int i = 0; i < 8; i++) atomicAdd(op + i, sum[i]);
    }
}

extern "C" void kernel_launch(void* const* d_in, const int* in_sizes, int n_in,
                              void* d_out, int out_size) {
    (void)in_sizes; (void)n_in; (void)out_size;
    const void*  idp  = d_in[0];
    const float* fmri = (const float*)d_in[1];
    const int*   idx  = (const int*)d_in[2];
    const float* Wt   = (const float*)d_in[3];
    const float* bias = (const float*)d_in[4];
    float* out = (float*)d_out;

    static bool attr_set = false;
    if (!attr_set) {
        cudaFuncSetAttribute(gemm_kernel,
                             cudaFuncAttributeMaxDynamicSharedMemorySize, SMEM_BYTES);
        attr_set = true;
    }

    setup_kernel<<<1, 32>>>(idp);
    init_out_kernel<<<(B_BATCH * OUT_DIMN + 255) / 256, 256>>>(out, bias);
    gather_kernel<<<dim3((K_VOX + 255) / 256, B_BATCH), 256>>>(fmri, idx);
    gemm_kernel<<<dim3(OUT_DIMN / OT, 16, KSPLIT), 256, SMEM_BYTES>>>(Wt, out);
}

// round 15
// speedup vs baseline: 1.6718x; 1.0526x over previous
#include <cuda_runtime.h>
#include <cstdint>

#define S_SUBJ   4
#define B_BATCH  64
#define K_VOX    40000
#define OUT_DIMN 768
#define V_VOX    (64*64*48)

#define OT      96           // outputs per block tile
#define MT      16           // samples per block tile (= MMA M)
#define KSPLIT  50
#define KCHUNK  800          // 40000 / 50
#define KC      32           // K per smem chunk
#define NITER   (KCHUNK/KC)  // 25
#define STAGES  4            // depth-3 pipeline

#define WSTRIDE 36           // padded row stride (floats) -> conflict-free LDS.32
#define WS_F    (OT*WSTRIDE) // 3456 floats
#define GS_F    (MT*WSTRIDE) // 576 floats
#define STAGE_F (WS_F+GS_F)  // 4032 floats
#define STAGE_B (STAGE_F*4)  // 16128 B
#define SMEM_BYTES (STAGES*STAGE_B)   // 64512 B -> 3 blocks/SM

// -------- device scratch (allocation-free per harness rules) --------
__device__ float g_G[(size_t)B_BATCH * K_VOX];
__device__ int   g_subj[B_BATCH];
__device__ int   g_order[B_BATCH];
__device__ int   g_slotsubj[B_BATCH];
__device__ int   g_off[S_SUBJ + 1];

// -------- 1) grouping + dtype detection (parallel read, serial tail) --------
__global__ void setup_kernel(const void* idp) {
    __shared__ int sh_id64[B_BATCH], sh_id32[B_BATCH];
    __shared__ int sh_is64;
    const int* w = (const int*)idp;
    int t = threadIdx.x;          // 64 threads
    // candidate reads for both layouts
    sh_id64[t] = w[2 * t];
    sh_id32[t] = w[t];
    // int64 detection: high words all zero
    int hi = w[2 * t + 1];
    unsigned any = __ballot_sync(0xffffffffu, hi != 0);
    if ((t & 31) == 0) {
        if (t == 0) sh_is64 = 1;
    }
    __syncthreads();
    if (any != 0) sh_is64 = 0;    // any warp seeing nonzero high word -> int32
    __syncthreads();
    int s = sh_is64 ? sh_id64[t] : sh_id32[t];
    g_subj[t] = s;
    __syncthreads();
    if (t == 0) {
        int cnt[S_SUBJ];
        for (int i = 0; i < S_SUBJ; i++) cnt[i] = 0;
        for (int b = 0; b < B_BATCH; b++)
            cnt[sh_is64 ? sh_id64[b] : sh_id32[b]]++;
        int off = 0, pos[S_SUBJ];
        for (int i = 0; i < S_SUBJ; i++) { g_off[i] = off; pos[i] = off; off += cnt[i]; }
        g_off[S_SUBJ] = off;
        for (int b = 0; b < B_BATCH; b++) {
            int sb = sh_is64 ? sh_id64[b] : sh_id32[b];
            int p = pos[sb]++;
            g_order[p] = b;
            g_slotsubj[p] = sb;
        }
    }
}

// -------- 2) out = bias[subj[b]] --------
__global__ void init_out_kernel(float* out, const float* bias) {
    int i = blockIdx.x * blockDim.x + threadIdx.x;
    if (i >= B_BATCH * OUT_DIMN) return;
    int b = i / OUT_DIMN;
    int o = i - b * OUT_DIMN;
    out[i] = bias[g_subj[b] * OUT_DIMN + o];
}

// -------- 3) gather (pre-rounds G to tf32-RNA: A-side MMA truncation exact) ----
__global__ void gather_kernel(const float* __restrict__ fmri, const int* __restrict__ idx) {
    int slot = blockIdx.y;
    int k = blockIdx.x * blockDim.x + threadIdx.x;
    if (k >= K_VOX) return;
    int b = g_order[slot];
    int s = g_slotsubj[slot];
    float v = fmri[(size_t)b * V_VOX + idx[s * K_VOX + k]];
    uint32_t bits;
    asm("cvt.rna.tf32.f32 %0, %1;" : "=r"(bits) : "f"(v));
    g_G[(size_t)slot * K_VOX + k] = __uint_as_float(bits);
}

// -------- asm helpers --------
__device__ __forceinline__ void cp_async16(uint32_t smem_addr, const void* gptr) {
    asm volatile("cp.async.cg.shared.global [%0], [%1], 16;" :: "r"(smem_addr), "l"(gptr));
}
__device__ __forceinline__ void cp_commit() { asm volatile("cp.async.commit_group;"); }
__device__ __forceinline__ void cp_wait2() { asm volatile("cp.async.wait_group 2;"); }
__device__ __forceinline__ void cp_wait1() { asm volatile("cp.async.wait_group 1;"); }
__device__ __forceinline__ void cp_wait0() { asm volatile("cp.async.wait_group 0;"); }
__device__ __forceinline__ uint32_t tf32_rna(float f) {
    uint32_t r;
    asm("cvt.rna.tf32.f32 %0, %1;" : "=r"(r) : "f"(f));
    return r;
}
__device__ __forceinline__ void mma_tf32(float* c, uint32_t a0, uint32_t a1,
                                         uint32_t a2, uint32_t a3,
                                         uint32_t b0, uint32_t b1) {
    asm volatile(
        "mma.sync.aligned.m16n8k8.row.col.f32.tf32.tf32.f32 "
        "{%0,%1,%2,%3}, {%4,%5,%6,%7}, {%8,%9}, {%0,%1,%2,%3};"
        : "+f"(c[0]), "+f"(c[1]), "+f"(c[2]), "+f"(c[3])
        : "r"(a0), "r"(a1), "r"(a2), "r"(a3), "r"(b0), "r"(b1));
}

// -------- 4) grouped GEMM via mma.sync tf32 (HMMA) --------
// OT=96 x MT=16 x KCHUNK(800). Warp w: o-half (w&1)*48 (6 n8 frags),
// k-step kq=w>>1. 4-stage cp.async pipeline (depth 3), 3 blocks/SM.
__global__ void __launch_bounds__(256, 3) gemm_kernel(const float* __restrict__ Wt,
                                                      float* __restrict__ out) {
    extern __shared__ __align__(16) float smem[];

    int tid = threadIdx.x;
    int warp = tid >> 5;
    int lane = tid & 31;

    int s = blockIdx.y >> 2;
    int mtile = (blockIdx.y & 3) * MT;
    int off = g_off[s];
    int count = g_off[s + 1] - off;
    int rows = count - mtile;
    if (rows <= 0) return;
    if (rows > MT) rows = MT;

    int otile = blockIdx.x * OT;
    size_t k0 = (size_t)blockIdx.z * KCHUNK;

    uint32_t smem_b;
    asm("{ .reg .u64 t; cvta.to.shared.u64 t, %1; cvt.u32.u64 %0, t; }"
        : "=r"(smem_b) : "l"(smem));

    // ---- staging map: thread -> cell (t&7), row base (t>>3 : 0..31) ----
    int cell = tid & 7;
    int rb = tid >> 3;                  // 0..31; W rows rb, rb+32, rb+64
    const float* wbase = Wt + (size_t)(s * OUT_DIMN + otile + rb) * K_VOX + k0 + cell * 4;
    int mglob = mtile + rb;             // G row (only rb<16 issues G)
    int slot = off + (mglob < count ? mglob : count - 1);
    const float* gbase = g_G + (size_t)slot * K_VOX + k0 + cell * 4;
    uint32_t wdoff = rb * (WSTRIDE * 4) + cell * 16;

    // ---- compute map ----
    int ohalf = (warp & 1) * 48;
    int kq = warp >> 1;                 // k8-step 0..3
    int lg = lane >> 2;                 // 0..7
    int lt = lane & 3;                  // 0..3

    float acc[6][4];
#pragma unroll
    for (int j = 0; j < 6; j++)
#pragma unroll
        for (int r = 0; r < 4; r++) acc[j][r] = 0.f;

#define ISSUE(IT, ST)                                                          \
    do {                                                                       \
        uint32_t wsb = smem_b + (ST) * STAGE_B;                                \
        const float* wsrc = wbase + (IT) * KC;                                 \
        _Pragma("unroll")                                                      \
        for (int q = 0; q < 3; q++)                                            \
            cp_async16(wsb + wdoff + q * (32 * WSTRIDE * 4),                   \
                       wsrc + (size_t)(32 * q) * K_VOX);                       \
        if (rb < MT)                                                           \
            cp_async16(wsb + WS_F * 4 + wdoff, gbase + (IT) * KC);             \
        cp_commit();                                                           \
    } while (0)
    // global W row = otile + rb + 32q matches smem row rb + 32q (q=0..2).

    ISSUE(0, 0);
    ISSUE(1, 1);
    ISSUE(2, 2);

    int st = 0, wst = 3;

    for (int it = 0; it < NITER; it++) {
        // graduated tail waits: guarantee chunk it landed
        if (it + 3 <= NITER)      cp_wait2();
        else if (it + 2 <= NITER) cp_wait1();
        else                      cp_wait0();
        __syncthreads();
        if (it + 3 < NITER) {
            ISSUE(it + 3, wst);
            wst = (wst == STAGES - 1) ? 0 : wst + 1;
        }

        const float* ws = smem + st * STAGE_F;
        const float* gs = ws + WS_F;
        st = (st == STAGES - 1) ? 0 : st + 1;

        {
            int kb = kq * 8 + lt;
            const float* ga = &gs[lg * WSTRIDE + kb];
            uint32_t a0 = __float_as_uint(ga[0]);
            uint32_t a1 = __float_as_uint(ga[8 * WSTRIDE]);
            uint32_t a2 = __float_as_uint(ga[4]);
            uint32_t a3 = __float_as_uint(ga[8 * WSTRIDE + 4]);
            const float* wb = &ws[(ohalf + lg) * WSTRIDE + kb];
#pragma unroll
            for (int j = 0; j < 6; j++) {
                uint32_t b0 = tf32_rna(wb[j * 8 * WSTRIDE]);
                uint32_t b1 = tf32_rna(wb[j * 8 * WSTRIDE + 4]);
                mma_tf32(acc[j], a0, a1, a2, a3, b0, b1);
            }
        }
    }
#undef ISSUE

    // ---- kq reduction in smem, then atomics ----
    __syncthreads();
    const int RS = 100;   // 96 + 4 pad
    float* red = smem;    // 4*16*100 = 6400 floats (< STAGES*STAGE_F)
#pragma unroll
    for (int j = 0; j < 6; j++) {
        int o = ohalf + j * 8 + lt * 2;
        float* r0 = &red[(kq * MT + lg) * RS + o];
        r0[0] = acc[j][0];
        r0[1] = acc[j][1];
        r0[8 * RS] = acc[j][2];
        r0[8 * RS + 1] = acc[j][3];
    }
    __syncthreads();
    int rm = tid >> 4;            // 0..15
    int oc = (tid & 15) * 6;      // 6 outputs per thread (96/16)
    if (rm < rows) {
        float sum[6];
#pragma unroll
        for (int i = 0; i < 6; i++) sum[i] = 0.f;
#pragma unroll
        for (int q = 0; q < 4; q++) {
            const float* rp = &red[(q * MT + rm) * RS + oc];
#pragma unroll
            for (int i = 0; i < 6; i++) sum[i] += rp[i];
        }
        int b = g_order[off + mtile + rm];
        float* op = &out[b * OUT_DIMN + otile + oc];
#pragma unroll
        for (int i = 0; i < 6; i++) atomicAdd(op + i, sum[i]);
    }
}

extern "C" void kernel_launch(void* const* d_in, const int* in_sizes, int n_in,
                              void* d_out, int out_size) {
    (void)in_sizes; (void)n_in; (void)out_size;
    const void*  idp  = d_in[0];
    const float* fmri = (const float*)d_in[1];
    const int*   idx  = (const int*)d_in[2];
    const float* Wt   = (const float*)d_in[3];
    const float* bias = (const float*)d_in[4];
    float* out = (float*)d_out;

    static bool attr_set = false;
    if (!attr_set) {
        cudaFuncSetAttribute(gemm_kernel,
                             cudaFuncAttributeMaxDynamicSharedMemorySize, SMEM_BYTES);
        attr_set = true;
    }

    setup_kernel<<<1, 64>>>(idp);
    init_out_kernel<<<(B_BATCH * OUT_DIMN + 255) / 256, 256>>>(out, bias);
    gather_kernel<<<dim3((K_VOX + 255) / 256, B_BATCH), 256>>>(fmri, idx);
    gemm_kernel<<<dim3(OUT_DIMN / OT, 16, KSPLIT), 256, SMEM_BYTES>>>(Wt, out);
}

// round 16
// speedup vs baseline: 1.9572x; 1.1708x over previous
#include <cuda_runtime.h>
#include <cuda.h>
#include <cstdint>
#include <dlfcn.h>

#define S_SUBJ   4
#define B_BATCH  64
#define K_VOX    40000
#define OUT_DIMN 768
#define V_VOX    (64*64*48)

#define OT      96           // outputs per block tile
#define MT      16           // samples per block tile (= MMA M)
#define KSPLIT  50
#define KCHUNK  800          // 40000 / 50
#define KC      32           // K per smem chunk
#define NITER   (KCHUNK/KC)  // 25

// ---- TMA kernel layout: dense SW128 tiles, 128B row pitch ----
#define T_STAGES  5
#define T_WBYTES  (OT*128)          // 12288
#define T_STAGE_B (T_WBYTES + MT*128)  // 14336 (multiple of 1024)
#define T_SMEM    (T_STAGES*T_STAGE_B + 1024)   // 72704 -> 3 blocks/SM

// ---- fallback (LDGSTS) layout ----
#define WSTRIDE 36
#define WS_F    (OT*WSTRIDE)
#define GS_F    (MT*WSTRIDE)
#define STAGE_F (WS_F+GS_F)
#define STAGE_B (STAGE_F*4)
#define F_STAGES 4
#define F_SMEM  (F_STAGES*STAGE_B)   // 64512

// -------- device scratch (allocation-free per harness rules) --------
__device__ __align__(256) float g_G[(size_t)B_BATCH * K_VOX];
__device__ int   g_subj[B_BATCH];
__device__ int   g_order[B_BATCH];
__device__ int   g_slotsubj[B_BATCH];
__device__ int   g_off[S_SUBJ + 1];

// -------- 1) grouping + dtype detection --------
__global__ void setup_kernel(const void* idp) {
    __shared__ int sh_id64[B_BATCH], sh_id32[B_BATCH];
    __shared__ int sh_is64;
    const int* w = (const int*)idp;
    int t = threadIdx.x;          // 64 threads
    sh_id64[t] = w[2 * t];
    sh_id32[t] = w[t];
    int hi = w[2 * t + 1];
    unsigned any = __ballot_sync(0xffffffffu, hi != 0);
    if (t == 0) sh_is64 = 1;
    __syncthreads();
    if (any != 0) sh_is64 = 0;
    __syncthreads();
    g_subj[t] = sh_is64 ? sh_id64[t] : sh_id32[t];
    __syncthreads();
    if (t == 0) {
        int cnt[S_SUBJ];
        for (int i = 0; i < S_SUBJ; i++) cnt[i] = 0;
        for (int b = 0; b < B_BATCH; b++)
            cnt[sh_is64 ? sh_id64[b] : sh_id32[b]]++;
        int off = 0, pos[S_SUBJ];
        for (int i = 0; i < S_SUBJ; i++) { g_off[i] = off; pos[i] = off; off += cnt[i]; }
        g_off[S_SUBJ] = off;
        for (int b = 0; b < B_BATCH; b++) {
            int sb = sh_is64 ? sh_id64[b] : sh_id32[b];
            int p = pos[sb]++;
            g_order[p] = b;
            g_slotsubj[p] = sb;
        }
    }
}

// -------- 2) out = bias[subj[b]] --------
__global__ void init_out_kernel(float* out, const float* bias) {
    int i = blockIdx.x * blockDim.x + threadIdx.x;
    if (i >= B_BATCH * OUT_DIMN) return;
    int b = i / OUT_DIMN;
    int o = i - b * OUT_DIMN;
    out[i] = bias[g_subj[b] * OUT_DIMN + o];
}

// -------- 3) gather (pre-rounds G to tf32-RNA) --------
__global__ void gather_kernel(const float* __restrict__ fmri, const int* __restrict__ idx) {
    int slot = blockIdx.y;
    int k = blockIdx.x * blockDim.x + threadIdx.x;
    if (k >= K_VOX) return;
    int b = g_order[slot];
    int s = g_slotsubj[slot];
    float v = fmri[(size_t)b * V_VOX + idx[s * K_VOX + k]];
    uint32_t bits;
    asm("cvt.rna.tf32.f32 %0, %1;" : "=r"(bits) : "f"(v));
    g_G[(size_t)slot * K_VOX + k] = __uint_as_float(bits);
}

// -------- asm helpers --------
__device__ __forceinline__ uint32_t smem_u32(const void* p) {
    uint32_t a;
    asm("{ .reg .u64 t; cvta.to.shared.u64 t, %1; cvt.u32.u64 %0, t; }" : "=r"(a) : "l"(p));
    return a;
}
__device__ __forceinline__ void cp_async16(uint32_t smem_addr, const void* gptr) {
    asm volatile("cp.async.cg.shared.global [%0], [%1], 16;" :: "r"(smem_addr), "l"(gptr));
}
__device__ __forceinline__ void cp_commit() { asm volatile("cp.async.commit_group;"); }
__device__ __forceinline__ void cp_wait2() { asm volatile("cp.async.wait_group 2;"); }
__device__ __forceinline__ void cp_wait1() { asm volatile("cp.async.wait_group 1;"); }
__device__ __forceinline__ void cp_wait0() { asm volatile("cp.async.wait_group 0;"); }
__device__ __forceinline__ void mbar_init(uint32_t a, uint32_t c) {
    asm volatile("mbarrier.init.shared.b64 [%0], %1;" :: "r"(a), "r"(c) : "memory");
}
__device__ __forceinline__ void mbar_expect(uint32_t a, uint32_t bytes) {
    asm volatile("mbarrier.arrive.expect_tx.shared.b64 _, [%0], %1;"
                 :: "r"(a), "r"(bytes) : "memory");
}
__device__ __forceinline__ void mbar_wait(uint32_t a, int parity) {
    asm volatile(
        "{\n\t.reg .pred P;\n\t"
        "W_%=:\n\t"
        "mbarrier.try_wait.parity.acquire.cta.shared::cta.b64 P, [%0], %1, 0x989680;\n\t"
        "@!P bra W_%=;\n\t}"
        :: "r"(a), "r"(parity) : "memory");
}
__device__ __forceinline__ void tma2d(uint32_t dst, const void* map, int x, int y,
                                      uint32_t mbar) {
    asm volatile(
        "cp.async.bulk.tensor.2d.shared::cta.global.tile.mbarrier::complete_tx::bytes "
        "[%0], [%1, {%2, %3}], [%4];"
        :: "r"(dst), "l"(map), "r"(x), "r"(y), "r"(mbar) : "memory");
}
__device__ __forceinline__ uint32_t lds_u(uint32_t a) {
    uint32_t v;
    asm volatile("ld.shared.b32 %0, [%1];" : "=r"(v) : "r"(a));
    return v;
}
__device__ __forceinline__ float lds_f(uint32_t a) {
    float v;
    asm volatile("ld.shared.f32 %0, [%1];" : "=f"(v) : "r"(a));
    return v;
}
__device__ __forceinline__ uint32_t tf32_rna(float f) {
    uint32_t r;
    asm("cvt.rna.tf32.f32 %0, %1;" : "=r"(r) : "f"(f));
    return r;
}
__device__ __forceinline__ void mma_tf32(float* c, uint32_t a0, uint32_t a1,
                                         uint32_t a2, uint32_t a3,
                                         uint32_t b0, uint32_t b1) {
    asm volatile(
        "mma.sync.aligned.m16n8k8.row.col.f32.tf32.tf32.f32 "
        "{%0,%1,%2,%3}, {%4,%5,%6,%7}, {%8,%9}, {%0,%1,%2,%3};"
        : "+f"(c[0]), "+f"(c[1]), "+f"(c[2]), "+f"(c[3])
        : "r"(a0), "r"(a1), "r"(a2), "r"(a3), "r"(b0), "r"(b1));
}

// -------- shared epilogue: kq-reduction in smem, then atomics --------
__device__ __forceinline__ void epilogue(float* red, float acc[6][4], int ohalf,
                                         int kq, int lg, int lt, int tid, int rows,
                                         int off, int mtile, int otile,
                                         float* __restrict__ out) {
    const int RS = 100;
#pragma unroll
    for (int j = 0; j < 6; j++) {
        int o = ohalf + j * 8 + lt * 2;
        float* r0 = &red[(kq * MT + lg) * RS + o];
        r0[0] = acc[j][0];
        r0[1] = acc[j][1];
        r0[8 * RS] = acc[j][2];
        r0[8 * RS + 1] = acc[j][3];
    }
    __syncthreads();
    int rm = tid >> 4;
    int oc = (tid & 15) * 6;
    if (rm < rows) {
        float sum[6];
#pragma unroll
        for (int i = 0; i < 6; i++) sum[i] = 0.f;
#pragma unroll
        for (int q = 0; q < 4; q++) {
            const float* rp = &red[(q * MT + rm) * RS + oc];
#pragma unroll
            for (int i = 0; i < 6; i++) sum[i] += rp[i];
        }
        int b = g_order[off + mtile + rm];
        float* op = &out[b * OUT_DIMN + otile + oc];
#pragma unroll
        for (int i = 0; i < 6; i++) atomicAdd(op + i, sum[i]);
    }
}

// -------- 4a) TMA-fed GEMM (mma.sync tf32) --------
__global__ void __launch_bounds__(256, 3) gemm_tma(
    const __grid_constant__ CUtensorMap wmap,
    const __grid_constant__ CUtensorMap gmap,
    float* __restrict__ out) {
    extern __shared__ __align__(16) char dsm[];
    __shared__ __align__(16) unsigned long long s_mbar[T_STAGES];

    int tid = threadIdx.x;
    int warp = tid >> 5;
    int lane = tid & 31;

    int s = blockIdx.y >> 2;
    int mtile = (blockIdx.y & 3) * MT;
    int off = g_off[s];
    int count = g_off[s + 1] - off;
    int rows = count - mtile;
    if (rows <= 0) return;
    if (rows > MT) rows = MT;

    int otile = blockIdx.x * OT;
    int k0 = blockIdx.z * KCHUNK;

    uint32_t base = (smem_u32(dsm) + 1023u) & ~1023u;   // 1024-align for SW128
    uint32_t mb0 = smem_u32(&s_mbar[0]);
    if (tid < T_STAGES) mbar_init(mb0 + tid * 8, 1);
    __syncthreads();

    int wrow = s * OUT_DIMN + otile;
    int grow = off + mtile;      // OOB rows zero-filled by TMA

#define TISSUE(IT, ST)                                                         \
    do {                                                                       \
        if (tid == 0) {                                                        \
            uint32_t mb = mb0 + (ST) * 8;                                      \
            mbar_expect(mb, T_STAGE_B);                                        \
            tma2d(base + (ST) * T_STAGE_B, &wmap, k0 + (IT) * KC, wrow, mb);   \
            tma2d(base + (ST) * T_STAGE_B + T_WBYTES, &gmap,                   \
                  k0 + (IT) * KC, grow, mb);                                   \
        }                                                                      \
    } while (0)

    TISSUE(0, 0); TISSUE(1, 1); TISSUE(2, 2); TISSUE(3, 3);

    int ohalf = (warp & 1) * 48;
    int kq = warp >> 1;
    int lg = lane >> 2;
    int lt = lane & 3;
    // swizzled in-row byte offsets (r&7 == lg for every row we touch)
    uint32_t off0 = ((uint32_t)((2 * kq) ^ lg) << 4) + lt * 4;
    uint32_t off1 = ((uint32_t)((2 * kq + 1) ^ lg) << 4) + lt * 4;

    float acc[6][4];
#pragma unroll
    for (int j = 0; j < 6; j++)
#pragma unroll
        for (int r = 0; r < 4; r++) acc[j][r] = 0.f;

    int st = 0, wst = 4;
    for (int it = 0; it < NITER; it++) {
        __syncthreads();                 // gates stage reuse (compute it-1 done)
        if (it + 4 < NITER) {
            TISSUE(it + 4, wst);
            wst = (wst == T_STAGES - 1) ? 0 : wst + 1;
        }
        mbar_wait(mb0 + st * 8, (it / T_STAGES) & 1);

        uint32_t wb_ = base + st * T_STAGE_B;
        uint32_t gb_ = wb_ + T_WBYTES;
        st = (st == T_STAGES - 1) ? 0 : st + 1;

        uint32_t a0 = lds_u(gb_ + lg * 128 + off0);
        uint32_t a1 = lds_u(gb_ + (lg + 8) * 128 + off0);
        uint32_t a2 = lds_u(gb_ + lg * 128 + off1);
        uint32_t a3 = lds_u(gb_ + (lg + 8) * 128 + off1);
#pragma unroll
        for (int j = 0; j < 6; j++) {
            uint32_t wr = wb_ + (ohalf + lg + 8 * j) * 128;
            uint32_t b0 = tf32_rna(lds_f(wr + off0));
            uint32_t b1 = tf32_rna(lds_f(wr + off1));
            mma_tf32(acc[j], a0, a1, a2, a3, b0, b1);
        }
    }
#undef TISSUE

    __syncthreads();
    float* red = (float*)(((uintptr_t)dsm + 1023) & ~(uintptr_t)1023);
    epilogue(red, acc, ohalf, kq, lg, lt, tid, rows, off, mtile, otile, out);
}

// -------- 4b) fallback: LDGSTS-fed GEMM (R14) --------
__global__ void __launch_bounds__(256, 3) gemm_fb(const float* __restrict__ Wt,
                                                  float* __restrict__ out) {
    extern __shared__ __align__(16) float smem[];

    int tid = threadIdx.x;
    int warp = tid >> 5;
    int lane = tid & 31;

    int s = blockIdx.y >> 2;
    int mtile = (blockIdx.y & 3) * MT;
    int off = g_off[s];
    int count = g_off[s + 1] - off;
    int rows = count - mtile;
    if (rows <= 0) return;
    if (rows > MT) rows = MT;

    int otile = blockIdx.x * OT;
    size_t k0 = (size_t)blockIdx.z * KCHUNK;

    uint32_t smem_b = smem_u32(smem);

    int cell = tid & 7;
    int rb = tid >> 3;
    const float* wbase = Wt + (size_t)(s * OUT_DIMN + otile + rb) * K_VOX + k0 + cell * 4;
    int mglob = mtile + rb;
    int slot = off + (mglob < count ? mglob : count - 1);
    const float* gbase = g_G + (size_t)slot * K_VOX + k0 + cell * 4;
    uint32_t wdoff = rb * (WSTRIDE * 4) + cell * 16;

    int ohalf = (warp & 1) * 48;
    int kq = warp >> 1;
    int lg = lane >> 2;
    int lt = lane & 3;

    float acc[6][4];
#pragma unroll
    for (int j = 0; j < 6; j++)
#pragma unroll
        for (int r = 0; r < 4; r++) acc[j][r] = 0.f;

#define ISSUE(IT, ST)                                                          \
    do {                                                                       \
        uint32_t wsb = smem_b + (ST) * STAGE_B;                                \
        const float* wsrc = wbase + (IT) * KC;                                 \
        _Pragma("unroll")                                                      \
        for (int q = 0; q < 3; q++)                                            \
            cp_async16(wsb + wdoff + q * (32 * WSTRIDE * 4),                   \
                       wsrc + (size_t)(32 * q) * K_VOX);                       \
        if (rb < MT)                                                           \
            cp_async16(wsb + WS_F * 4 + wdoff, gbase + (IT) * KC);             \
        cp_commit();                                                           \
    } while (0)

    ISSUE(0, 0); ISSUE(1, 1); ISSUE(2, 2);

    int st = 0, wst = 3;
    for (int it = 0; it < NITER; it++) {
        if (it + 3 <= NITER)      cp_wait2();
        else if (it + 2 <= NITER) cp_wait1();
        else                      cp_wait0();
        __syncthreads();
        if (it + 3 < NITER) {
            ISSUE(it + 3, wst);
            wst = (wst == F_STAGES - 1) ? 0 : wst + 1;
        }

        const float* ws = smem + st * STAGE_F;
        const float* gs = ws + WS_F;
        st = (st == F_STAGES - 1) ? 0 : st + 1;

        int kb = kq * 8 + lt;
        const float* ga = &gs[lg * WSTRIDE + kb];
        uint32_t a0 = __float_as_uint(ga[0]);
        uint32_t a1 = __float_as_uint(ga[8 * WSTRIDE]);
        uint32_t a2 = __float_as_uint(ga[4]);
        uint32_t a3 = __float_as_uint(ga[8 * WSTRIDE + 4]);
        const float* wb = &ws[(ohalf + lg) * WSTRIDE + kb];
#pragma unroll
        for (int j = 0; j < 6; j++) {
            uint32_t b0 = tf32_rna(wb[j * 8 * WSTRIDE]);
            uint32_t b1 = tf32_rna(wb[j * 8 * WSTRIDE + 4]);
            mma_tf32(acc[j], a0, a1, a2, a3, b0, b1);
        }
    }
#undef ISSUE

    __syncthreads();
    epilogue(smem, acc, ohalf, kq, lg, lt, tid, rows, off, mtile, otile, out);
}

// -------- host --------
typedef CUresult (*EncodeFn)(CUtensorMap*, CUtensorMapDataType, cuuint32_t, void*,
                             const cuuint64_t*, const cuuint64_t*, const cuuint32_t*,
                             const cuuint32_t*, CUtensorMapInterleave,
                             CUtensorMapSwizzle, CUtensorMapL2promotion,
                             CUtensorMapFloatOOBfill);

extern "C" void kernel_launch(void* const* d_in, const int* in_sizes, int n_in,
                              void* d_out, int out_size) {
    (void)in_sizes; (void)n_in; (void)out_size;
    const void*  idp  = d_in[0];
    const float* fmri = (const float*)d_in[1];
    const int*   idx  = (const int*)d_in[2];
    const float* Wt   = (const float*)d_in[3];
    const float* bias = (const float*)d_in[4];
    float* out = (float*)d_out;

    static int inited = 0;
    static EncodeFn enc = nullptr;
    if (!inited) {
        inited = 1;
        void* h = dlopen("libcuda.so.1", RTLD_LAZY | RTLD_GLOBAL);
        if (h) enc = (EncodeFn)dlsym(h, "cuTensorMapEncodeTiled");
        cudaFuncSetAttribute(gemm_tma, cudaFuncAttributeMaxDynamicSharedMemorySize, T_SMEM);
        cudaFuncSetAttribute(gemm_fb, cudaFuncAttributeMaxDynamicSharedMemorySize, F_SMEM);
    }

    setup_kernel<<<1, 64>>>(idp);
    init_out_kernel<<<(B_BATCH * OUT_DIMN + 255) / 256, 256>>>(out, bias);
    gather_kernel<<<dim3((K_VOX + 255) / 256, B_BATCH), 256>>>(fmri, idx);

    bool tma_ok = false;
    if (enc) {
        void* gptr = nullptr;
        cudaGetSymbolAddress(&gptr, g_G);
        CUtensorMap wmap, gmap;
        cuuint64_t wdims[2] = {K_VOX, (cuuint64_t)S_SUBJ * OUT_DIMN};
        cuuint64_t gdims[2] = {K_VOX, B_BATCH};
        cuuint64_t strides[1] = {(cuuint64_t)K_VOX * 4};
        cuuint32_t wbox[2] = {KC, OT};
        cuuint32_t gbox[2] = {KC, MT};
        cuuint32_t estr[2] = {1, 1};
        CUresult r1 = enc(&wmap, CU_TENSOR_MAP_DATA_TYPE_FLOAT32, 2, (void*)Wt,
                          wdims, strides, wbox, estr, CU_TENSOR_MAP_INTERLEAVE_NONE,
                          CU_TENSOR_MAP_SWIZZLE_128B, CU_TENSOR_MAP_L2_PROMOTION_L2_128B,
                          CU_TENSOR_MAP_FLOAT_OOB_FILL_NONE);
        CUresult r2 = enc(&gmap, CU_TENSOR_MAP_DATA_TYPE_FLOAT32, 2, gptr,
                          gdims, strides, gbox, estr, CU_TENSOR_MAP_INTERLEAVE_NONE,
                          CU_TENSOR_MAP_SWIZZLE_128B, CU_TENSOR_MAP_L2_PROMOTION_L2_128B,
                          CU_TENSOR_MAP_FLOAT_OOB_FILL_NONE);
        if (r1 == CUDA_SUCCESS && r2 == CUDA_SUCCESS) {
            gemm_tma<<<dim3(OUT_DIMN / OT, 16, KSPLIT), 256, T_SMEM>>>(wmap, gmap, out);
            tma_ok = true;
        }
    }
    if (!tma_ok) {
        gemm_fb<<<dim3(OUT_DIMN / OT, 16, KSPLIT), 256, F_SMEM>>>(Wt, out);
    }
}